// round 2
// baseline (speedup 1.0000x reference)
#include <cuda_runtime.h>
#include <cuda_bf16.h>
#include <cstdint>

#define BATCH 2
#define CDIM  512
#define CQK   64
#define NDIM  4096

// ---------------- scratch (device globals; no allocation allowed) ----------------
__device__ __nv_bfloat16 g_Xt[BATCH][NDIM][CDIM];    // x transposed, bf16   (8 MB)
__device__ __nv_bfloat16 g_Wqk[2*CQK][CDIM];         // [wq; wk] bf16
__device__ float         g_bqk[2*CQK];               // [bq; bk]
__device__ __nv_bfloat16 g_Wv[CDIM][CDIM];           // wv bf16
__device__ __nv_bfloat16 g_QK[BATCH][NDIM][2*CQK];   // q|k per token        (2 MB)
__device__ __nv_bfloat16 g_V[BATCH][CDIM][NDIM];     // v in [c][n] layout   (8 MB)
__device__ float         g_S[BATCH][NDIM][NDIM];     // energies fp32        (134 MB)
__device__ __nv_bfloat16 g_A[BATCH][NDIM][NDIM];     // softmax(A) bf16      (67 MB)

// ---------------- mma.sync m16n8k16 bf16 ----------------
__device__ __forceinline__ void mma16816(float c[4], const uint32_t a[4], const uint32_t b[2]) {
    asm volatile(
        "mma.sync.aligned.m16n8k16.row.col.f32.bf16.bf16.f32 "
        "{%0,%1,%2,%3}, {%4,%5,%6,%7}, {%8,%9}, {%0,%1,%2,%3};\n"
        : "+f"(c[0]), "+f"(c[1]), "+f"(c[2]), "+f"(c[3])
        : "r"(a[0]), "r"(a[1]), "r"(a[2]), "r"(a[3]), "r"(b[0]), "r"(b[1]));
}

// Tile config: BM=128, BN=64, BK=64; 256 threads = 8 warps (4x2), warp tile 32x32.
#define BM  128
#define BN  64
#define BK  64
#define BKP 72   // padded pitch (144B: 16B-aligned, conflict-free frag loads)

// Shared GEMM mainloop: C[BM,BN] += A[BM,K] * Bt[BN,K]^T  (both tiles stored [row][k])
__device__ __forceinline__ void gemm_mainloop(
    const __nv_bfloat16* __restrict__ Ag, int lda,
    const __nv_bfloat16* __restrict__ Bg, int ldb,
    int Ktiles, float (&acc)[2][4][4])
{
    __shared__ __nv_bfloat16 As[BM][BKP];
    __shared__ __nv_bfloat16 Bs[BN][BKP];

    const int tid  = threadIdx.x;
    const int lane = tid & 31, warp = tid >> 5;
    const int wm = warp >> 1, wn = warp & 1;
    const int r = lane >> 2, q = lane & 3;
    const int lrow = tid >> 3;          // 0..31
    const int lvec = (tid & 7) * 8;     // 0..56, 16B vectors

    for (int kt = 0; kt < Ktiles; kt++) {
        const __nv_bfloat16* a = Ag + kt * BK;
        const __nv_bfloat16* b = Bg + kt * BK;
        #pragma unroll
        for (int i = 0; i < 4; i++)
            *(uint4*)&As[lrow + i*32][lvec] = *(const uint4*)&a[(size_t)(lrow + i*32) * lda + lvec];
        #pragma unroll
        for (int i = 0; i < 2; i++)
            *(uint4*)&Bs[lrow + i*32][lvec] = *(const uint4*)&b[(size_t)(lrow + i*32) * ldb + lvec];
        __syncthreads();

        #pragma unroll
        for (int kk = 0; kk < BK; kk += 16) {
            uint32_t af[2][4], bf[4][2];
            #pragma unroll
            for (int mi = 0; mi < 2; mi++) {
                const int row = wm*32 + mi*16 + r;
                af[mi][0] = *(const uint32_t*)&As[row    ][kk + 2*q];
                af[mi][1] = *(const uint32_t*)&As[row + 8][kk + 2*q];
                af[mi][2] = *(const uint32_t*)&As[row    ][kk + 8 + 2*q];
                af[mi][3] = *(const uint32_t*)&As[row + 8][kk + 8 + 2*q];
            }
            #pragma unroll
            for (int ni = 0; ni < 4; ni++) {
                const int col = wn*32 + ni*8 + r;
                bf[ni][0] = *(const uint32_t*)&Bs[col][kk + 2*q];
                bf[ni][1] = *(const uint32_t*)&Bs[col][kk + 8 + 2*q];
            }
            #pragma unroll
            for (int mi = 0; mi < 2; mi++)
                #pragma unroll
                for (int ni = 0; ni < 4; ni++)
                    mma16816(acc[mi][ni], af[mi], bf[ni]);
        }
        __syncthreads();
    }
}

// ---------------- kernel 1: transpose+convert x -> Xt bf16 ----------------
__global__ void k_convert_x(const float* __restrict__ x) {
    __shared__ float tile[32][33];
    const int b  = blockIdx.z;
    const int n0 = blockIdx.x * 32, c0 = blockIdx.y * 32;
    const int tx = threadIdx.x, ty = threadIdx.y;   // (32, 8)
    #pragma unroll
    for (int i = 0; i < 32; i += 8)
        tile[ty + i][tx] = x[((size_t)(b*CDIM + c0 + ty + i)) * NDIM + n0 + tx];
    __syncthreads();
    #pragma unroll
    for (int i = 0; i < 32; i += 8)
        g_Xt[b][n0 + ty + i][c0 + tx] = __float2bfloat16(tile[tx][ty + i]);
}

// ---------------- kernel 2: convert weights/biases ----------------
__global__ void k_convert_w(const float* __restrict__ wq, const float* __restrict__ wk,
                            const float* __restrict__ wv,
                            const float* __restrict__ bq, const float* __restrict__ bk) {
    const int idx = blockIdx.x * 256 + threadIdx.x;
    if (idx < 32768) {
        ((__nv_bfloat16*)g_Wqk)[idx] = __float2bfloat16(wq[idx]);
    } else if (idx < 65536) {
        ((__nv_bfloat16*)g_Wqk)[idx] = __float2bfloat16(wk[idx - 32768]);
    } else if (idx < 65536 + 262144) {
        ((__nv_bfloat16*)g_Wv)[idx - 65536] = __float2bfloat16(wv[idx - 65536]);
    } else if (idx < 65536 + 262144 + 64) {
        g_bqk[idx - 327680] = bq[idx - 327680];
    } else if (idx < 65536 + 262144 + 128) {
        g_bqk[idx - 327680] = bk[idx - 327680 - 64];
    }
}

// ---------------- kernel 3: QK projection  QK[b][n][j] = Xt[n][:]*Wqk[j][:] + bqk[j] ----------------
__global__ void k_gemm_qk() {
    const int b = blockIdx.z, m0 = blockIdx.y * BM, n0 = blockIdx.x * BN;
    float acc[2][4][4] = {};
    gemm_mainloop(&g_Xt[b][m0][0], CDIM, &g_Wqk[n0][0], CDIM, CDIM / BK, acc);

    const int lane = threadIdx.x & 31, warp = threadIdx.x >> 5;
    const int wm = warp >> 1, wn = warp & 1, r = lane >> 2, q = lane & 3;
    #pragma unroll
    for (int mi = 0; mi < 2; mi++)
        #pragma unroll
        for (int ni = 0; ni < 4; ni++) {
            const int m = m0 + wm*32 + mi*16 + r;
            const int n = n0 + wn*32 + ni*8 + 2*q;
            const float b0 = g_bqk[n], b1 = g_bqk[n + 1];
            *(__nv_bfloat162*)&g_QK[b][m    ][n] = __floats2bfloat162_rn(acc[mi][ni][0] + b0, acc[mi][ni][1] + b1);
            *(__nv_bfloat162*)&g_QK[b][m + 8][n] = __floats2bfloat162_rn(acc[mi][ni][2] + b0, acc[mi][ni][3] + b1);
        }
}

// ---------------- kernel 4: V projection  V[b][c][n] = Wv[c][:]*Xt[n][:] + bv[c] ----------------
__global__ void k_gemm_v(const float* __restrict__ bv) {
    const int b = blockIdx.z, m0 = blockIdx.y * BM, n0 = blockIdx.x * BN;
    float acc[2][4][4] = {};
    gemm_mainloop(&g_Wv[m0][0], CDIM, &g_Xt[b][n0][0], CDIM, CDIM / BK, acc);

    const int lane = threadIdx.x & 31, warp = threadIdx.x >> 5;
    const int wm = warp >> 1, wn = warp & 1, r = lane >> 2, q = lane & 3;
    #pragma unroll
    for (int mi = 0; mi < 2; mi++) {
        const int m = m0 + wm*32 + mi*16 + r;
        const float bm0 = bv[m], bm8 = bv[m + 8];
        #pragma unroll
        for (int ni = 0; ni < 4; ni++) {
            const int n = n0 + wn*32 + ni*8 + 2*q;
            *(__nv_bfloat162*)&g_V[b][m    ][n] = __floats2bfloat162_rn(acc[mi][ni][0] + bm0, acc[mi][ni][1] + bm0);
            *(__nv_bfloat162*)&g_V[b][m + 8][n] = __floats2bfloat162_rn(acc[mi][ni][2] + bm8, acc[mi][ni][3] + bm8);
        }
    }
}

// ---------------- kernel 5: energies  S[b][i][j] = Q[i][:]·K[j][:] ----------------
__global__ void k_gemm_s() {
    const int b = blockIdx.z, m0 = blockIdx.y * BM, n0 = blockIdx.x * BN;
    float acc[2][4][4] = {};
    gemm_mainloop(&g_QK[b][m0][0], 2*CQK, &g_QK[b][n0][CQK], 2*CQK, 1, acc);

    const int lane = threadIdx.x & 31, warp = threadIdx.x >> 5;
    const int wm = warp >> 1, wn = warp & 1, r = lane >> 2, q = lane & 3;
    #pragma unroll
    for (int mi = 0; mi < 2; mi++)
        #pragma unroll
        for (int ni = 0; ni < 4; ni++) {
            const int m = m0 + wm*32 + mi*16 + r;
            const int n = n0 + wn*32 + ni*8 + 2*q;
            *(float2*)&g_S[b][m    ][n] = make_float2(acc[mi][ni][0], acc[mi][ni][1]);
            *(float2*)&g_S[b][m + 8][n] = make_float2(acc[mi][ni][2], acc[mi][ni][3]);
        }
}

// ---------------- kernel 6: row softmax, fp32 -> bf16 ----------------
__device__ __forceinline__ float blockReduceMax(float v) {
    __shared__ float sm[8];
    #pragma unroll
    for (int o = 16; o; o >>= 1) v = fmaxf(v, __shfl_xor_sync(0xffffffffu, v, o));
    if ((threadIdx.x & 31) == 0) sm[threadIdx.x >> 5] = v;
    __syncthreads();
    float r = sm[0];
    #pragma unroll
    for (int i = 1; i < 8; i++) r = fmaxf(r, sm[i]);
    __syncthreads();
    return r;
}
__device__ __forceinline__ float blockReduceSum(float v) {
    __shared__ float sm[8];
    #pragma unroll
    for (int o = 16; o; o >>= 1) v += __shfl_xor_sync(0xffffffffu, v, o);
    if ((threadIdx.x & 31) == 0) sm[threadIdx.x >> 5] = v;
    __syncthreads();
    float r = sm[0];
    #pragma unroll
    for (int i = 1; i < 8; i++) r += sm[i];
    __syncthreads();
    return r;
}

__global__ void k_softmax() {
    const size_t row = blockIdx.x;                        // 0..8191
    const float* __restrict__ src = ((const float*)g_S) + row * NDIM;
    __nv_bfloat16* __restrict__ dst = ((__nv_bfloat16*)g_A) + row * NDIM;
    const int tid = threadIdx.x;

    float v[16];
    float mx = -1e30f;
    #pragma unroll
    for (int i = 0; i < 16; i++) { v[i] = src[tid + i*256]; mx = fmaxf(mx, v[i]); }
    mx = blockReduceMax(mx);
    float s = 0.f;
    #pragma unroll
    for (int i = 0; i < 16; i++) { v[i] = __expf(v[i] - mx); s += v[i]; }
    s = blockReduceSum(s);
    const float inv = 1.0f / s;
    #pragma unroll
    for (int i = 0; i < 16; i++) dst[tid + i*256] = __float2bfloat16(v[i] * inv);
}

// ---------------- kernel 7: output  out[b][c][i] = gamma * (V[c][:]·A[i][:]) + x[b][c][i] ----------------
__global__ void k_gemm_o(const float* __restrict__ xin, const float* __restrict__ gma,
                         float* __restrict__ out) {
    const int b = blockIdx.z, m0 = blockIdx.y * BM, n0 = blockIdx.x * BN;
    float acc[2][4][4] = {};
    gemm_mainloop(&g_V[b][m0][0], NDIM, &g_A[b][n0][0], NDIM, NDIM / BK, acc);

    const float gm = gma[0];
    const int lane = threadIdx.x & 31, warp = threadIdx.x >> 5;
    const int wm = warp >> 1, wn = warp & 1, r = lane >> 2, q = lane & 3;
    #pragma unroll
    for (int mi = 0; mi < 2; mi++)
        #pragma unroll
        for (int ni = 0; ni < 4; ni++) {
            const int m = m0 + wm*32 + mi*16 + r;
            const int n = n0 + wn*32 + ni*8 + 2*q;
            const size_t i0 = ((size_t)(b*CDIM + m)) * NDIM + n;
            const size_t i8 = i0 + (size_t)8 * NDIM;
            float2 x0 = *(const float2*)&xin[i0];
            float2 x8 = *(const float2*)&xin[i8];
            float2 o0 = make_float2(gm * acc[mi][ni][0] + x0.x, gm * acc[mi][ni][1] + x0.y);
            float2 o8 = make_float2(gm * acc[mi][ni][2] + x8.x, gm * acc[mi][ni][3] + x8.y);
            *(float2*)&out[i0] = o0;
            *(float2*)&out[i8] = o8;
        }
}

// ---------------- launch ----------------
extern "C" void kernel_launch(void* const* d_in, const int* in_sizes, int n_in,
                              void* d_out, int out_size) {
    const float* x  = (const float*)d_in[0];
    // d_in[1] = s (unused by the reference)
    const float* wq = (const float*)d_in[2];
    const float* bq = (const float*)d_in[3];
    const float* wk = (const float*)d_in[4];
    const float* bk = (const float*)d_in[5];
    const float* wv = (const float*)d_in[6];
    const float* bv = (const float*)d_in[7];
    const float* gm = (const float*)d_in[8];
    float* out = (float*)d_out;

    k_convert_x<<<dim3(128, 16, 2), dim3(32, 8)>>>(x);
    k_convert_w<<<1281, 256>>>(wq, wk, wv, bq, bk);
    k_gemm_qk<<<dim3(2, 32, 2), 256>>>();
    k_gemm_v<<<dim3(64, 4, 2), 256>>>(bv);
    k_gemm_s<<<dim3(64, 32, 2), 256>>>();
    k_softmax<<<8192, 256>>>();
    k_gemm_o<<<dim3(64, 4, 2), 256>>>(x, gm, out);
}

// round 4
// speedup vs baseline: 1.4910x; 1.4910x over previous
#include <cuda_runtime.h>
#include <cuda_bf16.h>
#include <cstdint>

#define BATCH 2
#define CDIM  512
#define CQK   64
#define NDIM  4096

// GEMM tile config: BM=BN=128, BK=64, 256 threads = 8 warps (4m x 2n), warp tile 32x64
#define BM  128
#define BN  128
#define BK  64
#define BKP 72                      // padded pitch: 144B rows, conflict-free ldmatrix
#define STAGE (BM*BKP + BN*BKP)     // elements per pipeline stage
#define SMEM_BYTES (2 * STAGE * 2)  // 2 stages, bf16  = 73728 B

// ---------------- scratch (device globals; no allocation allowed) ----------------
__device__ __nv_bfloat16 g_Xt[BATCH][NDIM][CDIM];    // x transposed, bf16
__device__ __nv_bfloat16 g_Wqk[2*CQK][CDIM];         // [wq; wk] bf16
__device__ float         g_bqk[2*CQK];               // [bq; bk]
__device__ __nv_bfloat16 g_Wv[CDIM][CDIM];           // wv bf16
__device__ __nv_bfloat16 g_QK[BATCH][NDIM][2*CQK];   // q|k per token
__device__ __nv_bfloat16 g_V[BATCH][CDIM][NDIM];     // v in [c][n] layout
__device__ float         g_S[BATCH][NDIM][NDIM];     // energies fp32
__device__ __nv_bfloat16 g_A[BATCH][NDIM][NDIM];     // softmax(A) bf16

// ---------------- PTX helpers ----------------
__device__ __forceinline__ uint32_t smem_u32(const void* p) {
    return (uint32_t)__cvta_generic_to_shared(p);
}
__device__ __forceinline__ void cp16(void* dst, const void* src) {
    asm volatile("cp.async.cg.shared.global [%0], [%1], 16;\n"
                 :: "r"(smem_u32(dst)), "l"(src));
}
__device__ __forceinline__ void cp_commit() { asm volatile("cp.async.commit_group;\n"); }
template<int N> __device__ __forceinline__ void cp_wait() {
    asm volatile("cp.async.wait_group %0;\n" :: "n"(N));
}
__device__ __forceinline__ void ldsm4(uint32_t r[4], uint32_t addr) {
    asm volatile("ldmatrix.sync.aligned.m8n8.x4.shared.b16 {%0,%1,%2,%3}, [%4];\n"
                 : "=r"(r[0]), "=r"(r[1]), "=r"(r[2]), "=r"(r[3]) : "r"(addr));
}
__device__ __forceinline__ void mma16816(float c[4], const uint32_t a[4], const uint32_t b[2]) {
    asm volatile(
        "mma.sync.aligned.m16n8k16.row.col.f32.bf16.bf16.f32 "
        "{%0,%1,%2,%3}, {%4,%5,%6,%7}, {%8,%9}, {%0,%1,%2,%3};\n"
        : "+f"(c[0]), "+f"(c[1]), "+f"(c[2]), "+f"(c[3])
        : "r"(a[0]), "r"(a[1]), "r"(a[2]), "r"(a[3]), "r"(b[0]), "r"(b[1]));
}

// ---------------- pipelined GEMM mainloop: C[BM,BN] += A[BM,K] * B[BN,K]^T ----------------
__device__ __forceinline__ void gemm_pipe(
    const __nv_bfloat16* __restrict__ Ag, int lda,
    const __nv_bfloat16* __restrict__ Bg, int ldb,
    int Ktiles, float (&acc)[2][8][4])
{
    extern __shared__ __nv_bfloat16 smem[];
    const int tid  = threadIdx.x;
    const int lane = tid & 31, warp = tid >> 5;
    const int wm = warp >> 1, wn = warp & 1;
    const int lrow = tid >> 3;          // 0..31
    const int lvec = (tid & 7) * 8;     // 0..56 (16B vectors)

    // prologue: stage 0
    {
        __nv_bfloat16* as = smem;
        __nv_bfloat16* bs = smem + BM*BKP;
        #pragma unroll
        for (int i = 0; i < 4; i++) {
            const int r = lrow + i*32;
            cp16(&as[r*BKP + lvec], &Ag[(size_t)r * lda + lvec]);
        }
        #pragma unroll
        for (int i = 0; i < 4; i++) {
            const int r = lrow + i*32;
            cp16(&bs[r*BKP + lvec], &Bg[(size_t)r * ldb + lvec]);
        }
        cp_commit();
    }

    for (int kt = 0; kt < Ktiles; kt++) {
        const int s = kt & 1;
        if (kt + 1 < Ktiles) {
            __nv_bfloat16* as = smem + (s^1)*STAGE;
            __nv_bfloat16* bs = smem + (s^1)*STAGE + BM*BKP;
            const __nv_bfloat16* a = Ag + (size_t)(kt+1)*BK;
            const __nv_bfloat16* b = Bg + (size_t)(kt+1)*BK;
            #pragma unroll
            for (int i = 0; i < 4; i++) {
                const int r = lrow + i*32;
                cp16(&as[r*BKP + lvec], &a[(size_t)r * lda + lvec]);
            }
            #pragma unroll
            for (int i = 0; i < 4; i++) {
                const int r = lrow + i*32;
                cp16(&bs[r*BKP + lvec], &b[(size_t)r * ldb + lvec]);
            }
            cp_commit();
            cp_wait<1>();
        } else {
            cp_wait<0>();
        }
        __syncthreads();

        const __nv_bfloat16* as = smem + s*STAGE;
        const __nv_bfloat16* bs = smem + s*STAGE + BM*BKP;

        // ldmatrix lane address components
        const int a_r = (lane & 7) + (((lane >> 3) & 1) << 3);  // row within 16
        const int a_c = (lane >> 4) << 3;                       // 0 or 8
        const int b_r = (lane & 7) + ((lane >> 4) << 3);
        const int b_c = ((lane >> 3) & 1) << 3;

        #pragma unroll
        for (int kk = 0; kk < BK; kk += 16) {
            uint32_t af[2][4];
            #pragma unroll
            for (int mi = 0; mi < 2; mi++) {
                const int row = wm*32 + mi*16 + a_r;
                ldsm4(af[mi], smem_u32(&as[row*BKP + kk + a_c]));
            }
            uint32_t bfr[4][4];
            #pragma unroll
            for (int nj = 0; nj < 4; nj++) {
                const int row = wn*64 + nj*16 + b_r;
                ldsm4(bfr[nj], smem_u32(&bs[row*BKP + kk + b_c]));
            }
            #pragma unroll
            for (int mi = 0; mi < 2; mi++)
                #pragma unroll
                for (int nj = 0; nj < 4; nj++) {
                    mma16816(acc[mi][2*nj  ], af[mi], &bfr[nj][0]);
                    mma16816(acc[mi][2*nj+1], af[mi], &bfr[nj][2]);
                }
        }
        __syncthreads();
    }
}

// ---------------- kernel 1: transpose+convert x -> Xt bf16 ----------------
__global__ void k_convert_x(const float* __restrict__ x) {
    __shared__ float tile[32][33];
    const int b  = blockIdx.z;
    const int n0 = blockIdx.x * 32, c0 = blockIdx.y * 32;
    const int tx = threadIdx.x, ty = threadIdx.y;   // (32, 8)
    #pragma unroll
    for (int i = 0; i < 32; i += 8)
        tile[ty + i][tx] = x[((size_t)(b*CDIM + c0 + ty + i)) * NDIM + n0 + tx];
    __syncthreads();
    #pragma unroll
    for (int i = 0; i < 32; i += 8)
        g_Xt[b][n0 + ty + i][c0 + tx] = __float2bfloat16(tile[tx][ty + i]);
}

// ---------------- kernel 2: convert weights/biases ----------------
__global__ void k_convert_w(const float* __restrict__ wq, const float* __restrict__ wk,
                            const float* __restrict__ wv,
                            const float* __restrict__ bq, const float* __restrict__ bk) {
    const int idx = blockIdx.x * 256 + threadIdx.x;
    if (idx < 32768) {
        ((__nv_bfloat16*)g_Wqk)[idx] = __float2bfloat16(wq[idx]);
    } else if (idx < 65536) {
        ((__nv_bfloat16*)g_Wqk)[idx] = __float2bfloat16(wk[idx - 32768]);
    } else if (idx < 65536 + 262144) {
        ((__nv_bfloat16*)g_Wv)[idx - 65536] = __float2bfloat16(wv[idx - 65536]);
    } else if (idx < 65536 + 262144 + 64) {
        g_bqk[idx - 327680] = bq[idx - 327680];
    } else if (idx < 65536 + 262144 + 128) {
        g_bqk[idx - 327680] = bk[idx - 327680 - 64];
    }
}

// ---------------- kernel 3: QK projection ----------------
__global__ void __launch_bounds__(256, 2) k_gemm_qk() {
    const int b = blockIdx.z, m0 = blockIdx.y * BM;   // n0 = 0 (BN=128 covers all)
    float acc[2][8][4] = {};
    gemm_pipe(&g_Xt[b][m0][0], CDIM, &g_Wqk[0][0], CDIM, CDIM / BK, acc);

    const int lane = threadIdx.x & 31, warp = threadIdx.x >> 5;
    const int wm = warp >> 1, wn = warp & 1, r = lane >> 2, q = lane & 3;
    #pragma unroll
    for (int mi = 0; mi < 2; mi++)
        #pragma unroll
        for (int ni = 0; ni < 8; ni++) {
            const int m = m0 + wm*32 + mi*16 + r;
            const int n = wn*64 + ni*8 + 2*q;
            const float b0 = g_bqk[n], b1 = g_bqk[n + 1];
            *(__nv_bfloat162*)&g_QK[b][m    ][n] = __floats2bfloat162_rn(acc[mi][ni][0] + b0, acc[mi][ni][1] + b1);
            *(__nv_bfloat162*)&g_QK[b][m + 8][n] = __floats2bfloat162_rn(acc[mi][ni][2] + b0, acc[mi][ni][3] + b1);
        }
}

// ---------------- kernel 4: V projection ----------------
__global__ void __launch_bounds__(256, 2) k_gemm_v(const float* __restrict__ bv) {
    const int b = blockIdx.z, m0 = blockIdx.y * BM, n0 = blockIdx.x * BN;
    float acc[2][8][4] = {};
    gemm_pipe(&g_Wv[m0][0], CDIM, &g_Xt[b][n0][0], CDIM, CDIM / BK, acc);

    const int lane = threadIdx.x & 31, warp = threadIdx.x >> 5;
    const int wm = warp >> 1, wn = warp & 1, r = lane >> 2, q = lane & 3;
    #pragma unroll
    for (int mi = 0; mi < 2; mi++) {
        const int m = m0 + wm*32 + mi*16 + r;
        const float bm0 = bv[m], bm8 = bv[m + 8];
        #pragma unroll
        for (int ni = 0; ni < 8; ni++) {
            const int n = n0 + wn*64 + ni*8 + 2*q;
            *(__nv_bfloat162*)&g_V[b][m    ][n] = __floats2bfloat162_rn(acc[mi][ni][0] + bm0, acc[mi][ni][1] + bm0);
            *(__nv_bfloat162*)&g_V[b][m + 8][n] = __floats2bfloat162_rn(acc[mi][ni][2] + bm8, acc[mi][ni][3] + bm8);
        }
    }
}

// ---------------- kernel 5: energies S = Q K^T ----------------
__global__ void __launch_bounds__(256, 2) k_gemm_s() {
    const int b = blockIdx.z, m0 = blockIdx.y * BM, n0 = blockIdx.x * BN;
    float acc[2][8][4] = {};
    gemm_pipe(&g_QK[b][m0][0], 2*CQK, &g_QK[b][n0][CQK], 2*CQK, 1, acc);

    const int lane = threadIdx.x & 31, warp = threadIdx.x >> 5;
    const int wm = warp >> 1, wn = warp & 1, r = lane >> 2, q = lane & 3;
    #pragma unroll
    for (int mi = 0; mi < 2; mi++)
        #pragma unroll
        for (int ni = 0; ni < 8; ni++) {
            const int m = m0 + wm*32 + mi*16 + r;
            const int n = n0 + wn*64 + ni*8 + 2*q;
            *(float2*)&g_S[b][m    ][n] = make_float2(acc[mi][ni][0], acc[mi][ni][1]);
            *(float2*)&g_S[b][m + 8][n] = make_float2(acc[mi][ni][2], acc[mi][ni][3]);
        }
}

// ---------------- kernel 6: row softmax, fp32 -> bf16 (vectorized) ----------------
__device__ __forceinline__ float blockReduceMax(float v) {
    __shared__ float sm[8];
    #pragma unroll
    for (int o = 16; o; o >>= 1) v = fmaxf(v, __shfl_xor_sync(0xffffffffu, v, o));
    if ((threadIdx.x & 31) == 0) sm[threadIdx.x >> 5] = v;
    __syncthreads();
    float r = sm[0];
    #pragma unroll
    for (int i = 1; i < 8; i++) r = fmaxf(r, sm[i]);
    __syncthreads();
    return r;
}
__device__ __forceinline__ float blockReduceSum(float v) {
    __shared__ float sm[8];
    #pragma unroll
    for (int o = 16; o; o >>= 1) v += __shfl_xor_sync(0xffffffffu, v, o);
    if ((threadIdx.x & 31) == 0) sm[threadIdx.x >> 5] = v;
    __syncthreads();
    float r = sm[0];
    #pragma unroll
    for (int i = 1; i < 8; i++) r += sm[i];
    __syncthreads();
    return r;
}

__global__ void k_softmax() {
    const size_t row = blockIdx.x;                        // 0..8191
    const float4* __restrict__ src = (const float4*)(((const float*)g_S) + row * NDIM);
    uint2* __restrict__ dst = (uint2*)(((__nv_bfloat16*)g_A) + row * NDIM);
    const int t = threadIdx.x;

    float4 v[4];
    float mx = -1e30f;
    #pragma unroll
    for (int i = 0; i < 4; i++) {
        v[i] = src[t + i*256];
        mx = fmaxf(mx, fmaxf(fmaxf(v[i].x, v[i].y), fmaxf(v[i].z, v[i].w)));
    }
    mx = blockReduceMax(mx);
    float s = 0.f;
    #pragma unroll
    for (int i = 0; i < 4; i++) {
        v[i].x = __expf(v[i].x - mx); v[i].y = __expf(v[i].y - mx);
        v[i].z = __expf(v[i].z - mx); v[i].w = __expf(v[i].w - mx);
        s += (v[i].x + v[i].y) + (v[i].z + v[i].w);
    }
    s = blockReduceSum(s);
    const float inv = 1.0f / s;
    #pragma unroll
    for (int i = 0; i < 4; i++) {
        __nv_bfloat162 lo = __floats2bfloat162_rn(v[i].x * inv, v[i].y * inv);
        __nv_bfloat162 hi = __floats2bfloat162_rn(v[i].z * inv, v[i].w * inv);
        uint2 u;
        u.x = *(uint32_t*)&lo;
        u.y = *(uint32_t*)&hi;
        dst[t + i*256] = u;
    }
}

// ---------------- kernel 7: output  out = gamma * (V A^T) + x ----------------
__global__ void __launch_bounds__(256, 2) k_gemm_o(const float* __restrict__ xin,
                                                   const float* __restrict__ gma,
                                                   float* __restrict__ out) {
    const int b = blockIdx.z, m0 = blockIdx.y * BM, n0 = blockIdx.x * BN;
    float acc[2][8][4] = {};
    gemm_pipe(&g_V[b][m0][0], NDIM, &g_A[b][n0][0], NDIM, NDIM / BK, acc);

    const float gm = gma[0];
    const int lane = threadIdx.x & 31, warp = threadIdx.x >> 5;
    const int wm = warp >> 1, wn = warp & 1, r = lane >> 2, q = lane & 3;
    #pragma unroll
    for (int mi = 0; mi < 2; mi++)
        #pragma unroll
        for (int ni = 0; ni < 8; ni++) {
            const int m = m0 + wm*32 + mi*16 + r;
            const int n = n0 + wn*64 + ni*8 + 2*q;
            const size_t i0 = ((size_t)(b*CDIM + m)) * NDIM + n;
            const size_t i8 = i0 + (size_t)8 * NDIM;
            float2 x0 = *(const float2*)&xin[i0];
            float2 x8 = *(const float2*)&xin[i8];
            *(float2*)&out[i0] = make_float2(gm * acc[mi][ni][0] + x0.x, gm * acc[mi][ni][1] + x0.y);
            *(float2*)&out[i8] = make_float2(gm * acc[mi][ni][2] + x8.x, gm * acc[mi][ni][3] + x8.y);
        }
}

// ---------------- launch ----------------
extern "C" void kernel_launch(void* const* d_in, const int* in_sizes, int n_in,
                              void* d_out, int out_size) {
    const float* x  = (const float*)d_in[0];
    // d_in[1] = s (unused by the reference)
    const float* wq = (const float*)d_in[2];
    const float* bq = (const float*)d_in[3];
    const float* wk = (const float*)d_in[4];
    const float* bk = (const float*)d_in[5];
    const float* wv = (const float*)d_in[6];
    const float* bv = (const float*)d_in[7];
    const float* gm = (const float*)d_in[8];
    float* out = (float*)d_out;

    cudaFuncSetAttribute(k_gemm_qk, cudaFuncAttributeMaxDynamicSharedMemorySize, SMEM_BYTES);
    cudaFuncSetAttribute(k_gemm_v,  cudaFuncAttributeMaxDynamicSharedMemorySize, SMEM_BYTES);
    cudaFuncSetAttribute(k_gemm_s,  cudaFuncAttributeMaxDynamicSharedMemorySize, SMEM_BYTES);
    cudaFuncSetAttribute(k_gemm_o,  cudaFuncAttributeMaxDynamicSharedMemorySize, SMEM_BYTES);

    k_convert_x<<<dim3(128, 16, 2), dim3(32, 8)>>>(x);
    k_convert_w<<<1281, 256>>>(wq, wk, wv, bq, bk);
    k_gemm_qk<<<dim3(1, 32, 2),  256, SMEM_BYTES>>>();
    k_gemm_v <<<dim3(32, 4, 2),  256, SMEM_BYTES>>>(bv);
    k_gemm_s <<<dim3(32, 32, 2), 256, SMEM_BYTES>>>();
    k_softmax<<<8192, 256>>>();
    k_gemm_o <<<dim3(32, 4, 2),  256, SMEM_BYTES>>>(x, gm, out);
}

// round 5
// speedup vs baseline: 1.8280x; 1.2260x over previous
#include <cuda_runtime.h>
#include <cuda_bf16.h>
#include <cuda_fp16.h>
#include <cstdint>

#define BATCH 2
#define CDIM  512
#define CQK   64
#define NDIM  4096

// GEMM tile config: BM=BN=128, BK=64, 256 threads = 8 warps (4m x 2n), warp tile 32x64
#define BM  128
#define BN  128
#define BK  64
#define ROWB 128                    // bytes per smem row (BK * 2, exact, swizzled)
#define A_BYTES (BM * ROWB)         // 16384
#define STAGE_B (A_BYTES + BN*ROWB) // 32768 bytes per stage
#define STAGES 3
#define SMEM_BYTES (STAGES * STAGE_B)  // 98304

// ---------------- scratch (device globals; no allocation allowed) ----------------
__device__ __nv_bfloat16 g_Xt[BATCH][NDIM][CDIM];    // x transposed, bf16
__device__ __nv_bfloat16 g_Wqk[2*CQK][CDIM];         // [wq; wk] bf16
__device__ float         g_bqk[2*CQK];               // [bq; bk]
__device__ __nv_bfloat16 g_Wv[CDIM][CDIM];           // wv bf16
__device__ __nv_bfloat16 g_QK[BATCH][NDIM][2*CQK];   // q|k per token
__device__ __nv_bfloat16 g_V[BATCH][CDIM][NDIM];     // v in [c][n] layout
__device__ __half        g_Sh[BATCH][NDIM][NDIM];    // energies fp16 (67 MB)
__device__ __nv_bfloat16 g_A[BATCH][NDIM][NDIM];     // softmax(A) bf16

// ---------------- PTX helpers ----------------
__device__ __forceinline__ uint32_t smem_u32(const void* p) {
    return (uint32_t)__cvta_generic_to_shared(p);
}
__device__ __forceinline__ void cp16(uint32_t dst, const void* src) {
    asm volatile("cp.async.cg.shared.global [%0], [%1], 16;\n" :: "r"(dst), "l"(src));
}
__device__ __forceinline__ void cp_commit() { asm volatile("cp.async.commit_group;\n"); }
template<int N> __device__ __forceinline__ void cp_wait() {
    asm volatile("cp.async.wait_group %0;\n" :: "n"(N));
}
__device__ __forceinline__ void ldsm4(uint32_t r[4], uint32_t addr) {
    asm volatile("ldmatrix.sync.aligned.m8n8.x4.shared.b16 {%0,%1,%2,%3}, [%4];\n"
                 : "=r"(r[0]), "=r"(r[1]), "=r"(r[2]), "=r"(r[3]) : "r"(addr));
}
__device__ __forceinline__ void mma16816(float c[4], const uint32_t a[4], const uint32_t b[2]) {
    asm volatile(
        "mma.sync.aligned.m16n8k16.row.col.f32.bf16.bf16.f32 "
        "{%0,%1,%2,%3}, {%4,%5,%6,%7}, {%8,%9}, {%0,%1,%2,%3};\n"
        : "+f"(c[0]), "+f"(c[1]), "+f"(c[2]), "+f"(c[3])
        : "r"(a[0]), "r"(a[1]), "r"(a[2]), "r"(a[3]), "r"(b[0]), "r"(b[1]));
}
// SW128-style XOR swizzle on byte offsets (16B granularity preserved)
__device__ __forceinline__ uint32_t swz(uint32_t off) {
    return off ^ ((off >> 3) & 0x70);
}

// ---------------- 3-stage pipelined GEMM mainloop: C[BM,BN] += A[BM,K] * B[BN,K]^T ----------------
__device__ __forceinline__ void gemm_pipe(
    const __nv_bfloat16* __restrict__ Ag, int lda,
    const __nv_bfloat16* __restrict__ Bg, int ldb,
    int Ktiles, float (&acc)[2][8][4])
{
    extern __shared__ __align__(1024) char smem[];
    const uint32_t sbase = smem_u32(smem);
    const int tid  = threadIdx.x;
    const int lane = tid & 31, warp = tid >> 5;
    const int wm = warp >> 1, wn = warp & 1;
    const int lrow = tid >> 3;              // 0..31
    const int lcol = (tid & 7) * 16;        // byte col within 128B row

    // ldmatrix lane address components
    const int a_r = (lane & 7) + (((lane >> 3) & 1) << 3);
    const int a_c = ((lane >> 4) << 3) * 2;          // byte offset: 0 or 16
    const int b_r = (lane & 7) + ((lane >> 4) << 3);
    const int b_c = (((lane >> 3) & 1) << 3) * 2;

    auto load_tile = [&](int stage, int kt) {
        const uint32_t as = sbase + stage * STAGE_B;
        const uint32_t bs = as + A_BYTES;
        const __nv_bfloat16* a = Ag + (size_t)kt * BK;
        const __nv_bfloat16* b = Bg + (size_t)kt * BK;
        #pragma unroll
        for (int i = 0; i < 4; i++) {
            const int r = lrow + i*32;
            cp16(as + swz(r*ROWB + lcol), (const char*)(a + (size_t)r * lda) + lcol);
        }
        #pragma unroll
        for (int i = 0; i < 4; i++) {
            const int r = lrow + i*32;
            cp16(bs + swz(r*ROWB + lcol), (const char*)(b + (size_t)r * ldb) + lcol);
        }
        cp_commit();
    };

    // prologue: prefetch up to 2 tiles
    load_tile(0, 0);
    if (Ktiles > 1) load_tile(1, 1);

    for (int kt = 0; kt < Ktiles; kt++) {
        if (kt + 2 <= Ktiles) cp_wait<1>(); else cp_wait<0>();
        __syncthreads();
        if (kt + 2 < Ktiles) load_tile((kt + 2) % STAGES, kt + 2);

        const uint32_t as = sbase + (kt % STAGES) * STAGE_B;
        const uint32_t bs = as + A_BYTES;

        #pragma unroll
        for (int kk = 0; kk < BK; kk += 16) {
            uint32_t af[2][4];
            #pragma unroll
            for (int mi = 0; mi < 2; mi++) {
                const int row = wm*32 + mi*16 + a_r;
                ldsm4(af[mi], as + swz(row*ROWB + kk*2 + a_c));
            }
            uint32_t bfr[4][4];
            #pragma unroll
            for (int nj = 0; nj < 4; nj++) {
                const int row = wn*64 + nj*16 + b_r;
                ldsm4(bfr[nj], bs + swz(row*ROWB + kk*2 + b_c));
            }
            #pragma unroll
            for (int mi = 0; mi < 2; mi++)
                #pragma unroll
                for (int nj = 0; nj < 4; nj++) {
                    mma16816(acc[mi][2*nj  ], af[mi], &bfr[nj][0]);
                    mma16816(acc[mi][2*nj+1], af[mi], &bfr[nj][2]);
                }
        }
    }
}

// ---------------- kernel 1: transpose+convert x -> Xt bf16 ----------------
__global__ void k_convert_x(const float* __restrict__ x) {
    __shared__ float tile[32][33];
    const int b  = blockIdx.z;
    const int n0 = blockIdx.x * 32, c0 = blockIdx.y * 32;
    const int tx = threadIdx.x, ty = threadIdx.y;   // (32, 8)
    #pragma unroll
    for (int i = 0; i < 32; i += 8)
        tile[ty + i][tx] = x[((size_t)(b*CDIM + c0 + ty + i)) * NDIM + n0 + tx];
    __syncthreads();
    #pragma unroll
    for (int i = 0; i < 32; i += 8)
        g_Xt[b][n0 + ty + i][c0 + tx] = __float2bfloat16(tile[tx][ty + i]);
}

// ---------------- kernel 2: convert weights/biases ----------------
__global__ void k_convert_w(const float* __restrict__ wq, const float* __restrict__ wk,
                            const float* __restrict__ wv,
                            const float* __restrict__ bq, const float* __restrict__ bk) {
    const int idx = blockIdx.x * 256 + threadIdx.x;
    if (idx < 32768) {
        ((__nv_bfloat16*)g_Wqk)[idx] = __float2bfloat16(wq[idx]);
    } else if (idx < 65536) {
        ((__nv_bfloat16*)g_Wqk)[idx] = __float2bfloat16(wk[idx - 32768]);
    } else if (idx < 65536 + 262144) {
        ((__nv_bfloat16*)g_Wv)[idx - 65536] = __float2bfloat16(wv[idx - 65536]);
    } else if (idx < 65536 + 262144 + 64) {
        g_bqk[idx - 327680] = bq[idx - 327680];
    } else if (idx < 65536 + 262144 + 128) {
        g_bqk[idx - 327680] = bk[idx - 327680 - 64];
    }
}

// ---------------- kernel 3: QK projection ----------------
__global__ void __launch_bounds__(256, 2) k_gemm_qk() {
    const int b = blockIdx.z, m0 = blockIdx.y * BM;   // n0 = 0 (BN=128 covers all)
    float acc[2][8][4] = {};
    gemm_pipe(&g_Xt[b][m0][0], CDIM, &g_Wqk[0][0], CDIM, CDIM / BK, acc);

    const int lane = threadIdx.x & 31, warp = threadIdx.x >> 5;
    const int wm = warp >> 1, wn = warp & 1, r = lane >> 2, q = lane & 3;
    #pragma unroll
    for (int mi = 0; mi < 2; mi++)
        #pragma unroll
        for (int ni = 0; ni < 8; ni++) {
            const int m = m0 + wm*32 + mi*16 + r;
            const int n = wn*64 + ni*8 + 2*q;
            const float b0 = g_bqk[n], b1 = g_bqk[n + 1];
            *(__nv_bfloat162*)&g_QK[b][m    ][n] = __floats2bfloat162_rn(acc[mi][ni][0] + b0, acc[mi][ni][1] + b1);
            *(__nv_bfloat162*)&g_QK[b][m + 8][n] = __floats2bfloat162_rn(acc[mi][ni][2] + b0, acc[mi][ni][3] + b1);
        }
}

// ---------------- kernel 4: V projection ----------------
__global__ void __launch_bounds__(256, 2) k_gemm_v(const float* __restrict__ bv) {
    const int b = blockIdx.z, m0 = blockIdx.y * BM, n0 = blockIdx.x * BN;
    float acc[2][8][4] = {};
    gemm_pipe(&g_Wv[m0][0], CDIM, &g_Xt[b][n0][0], CDIM, CDIM / BK, acc);

    const int lane = threadIdx.x & 31, warp = threadIdx.x >> 5;
    const int wm = warp >> 1, wn = warp & 1, r = lane >> 2, q = lane & 3;
    #pragma unroll
    for (int mi = 0; mi < 2; mi++) {
        const int m = m0 + wm*32 + mi*16 + r;
        const float bm0 = bv[m], bm8 = bv[m + 8];
        #pragma unroll
        for (int ni = 0; ni < 8; ni++) {
            const int n = n0 + wn*64 + ni*8 + 2*q;
            *(__nv_bfloat162*)&g_V[b][m    ][n] = __floats2bfloat162_rn(acc[mi][ni][0] + bm0, acc[mi][ni][1] + bm0);
            *(__nv_bfloat162*)&g_V[b][m + 8][n] = __floats2bfloat162_rn(acc[mi][ni][2] + bm8, acc[mi][ni][3] + bm8);
        }
    }
}

// ---------------- kernel 5: energies S = Q K^T  (fp16 out) ----------------
__global__ void __launch_bounds__(256, 2) k_gemm_s() {
    const int b = blockIdx.z, m0 = blockIdx.y * BM, n0 = blockIdx.x * BN;
    float acc[2][8][4] = {};
    gemm_pipe(&g_QK[b][m0][0], 2*CQK, &g_QK[b][n0][CQK], 2*CQK, 1, acc);

    const int lane = threadIdx.x & 31, warp = threadIdx.x >> 5;
    const int wm = warp >> 1, wn = warp & 1, r = lane >> 2, q = lane & 3;
    #pragma unroll
    for (int mi = 0; mi < 2; mi++)
        #pragma unroll
        for (int ni = 0; ni < 8; ni++) {
            const int m = m0 + wm*32 + mi*16 + r;
            const int n = n0 + wn*64 + ni*8 + 2*q;
            *(__half2*)&g_Sh[b][m    ][n] = __floats2half2_rn(acc[mi][ni][0], acc[mi][ni][1]);
            *(__half2*)&g_Sh[b][m + 8][n] = __floats2half2_rn(acc[mi][ni][2], acc[mi][ni][3]);
        }
}

// ---------------- kernel 6: row softmax, fp16 -> bf16 (vectorized) ----------------
__device__ __forceinline__ float blockReduceMax(float v) {
    __shared__ float sm[8];
    #pragma unroll
    for (int o = 16; o; o >>= 1) v = fmaxf(v, __shfl_xor_sync(0xffffffffu, v, o));
    if ((threadIdx.x & 31) == 0) sm[threadIdx.x >> 5] = v;
    __syncthreads();
    float r = sm[0];
    #pragma unroll
    for (int i = 1; i < 8; i++) r = fmaxf(r, sm[i]);
    __syncthreads();
    return r;
}
__device__ __forceinline__ float blockReduceSum(float v) {
    __shared__ float sm[8];
    #pragma unroll
    for (int o = 16; o; o >>= 1) v += __shfl_xor_sync(0xffffffffu, v, o);
    if ((threadIdx.x & 31) == 0) sm[threadIdx.x >> 5] = v;
    __syncthreads();
    float r = sm[0];
    #pragma unroll
    for (int i = 1; i < 8; i++) r += sm[i];
    __syncthreads();
    return r;
}

__global__ void k_softmax() {
    const size_t row = blockIdx.x;                        // 0..8191
    const uint4* __restrict__ src = (const uint4*)(((const __half*)g_Sh) + row * NDIM);
    uint4* __restrict__ dst = (uint4*)(((__nv_bfloat16*)g_A) + row * NDIM);
    const int t = threadIdx.x;

    float v[16];
    #pragma unroll
    for (int i = 0; i < 2; i++) {
        uint4 u = src[t + i*256];
        const __half2* h = (const __half2*)&u;
        #pragma unroll
        for (int j = 0; j < 4; j++) {
            float2 f = __half22float2(h[j]);
            v[i*8 + 2*j    ] = f.x;
            v[i*8 + 2*j + 1] = f.y;
        }
    }
    float mx = v[0];
    #pragma unroll
    for (int i = 1; i < 16; i++) mx = fmaxf(mx, v[i]);
    mx = blockReduceMax(mx);
    float s = 0.f;
    #pragma unroll
    for (int i = 0; i < 16; i++) { v[i] = __expf(v[i] - mx); s += v[i]; }
    s = blockReduceSum(s);
    const float inv = 1.0f / s;
    #pragma unroll
    for (int i = 0; i < 2; i++) {
        uint4 u;
        uint32_t* w = (uint32_t*)&u;
        #pragma unroll
        for (int j = 0; j < 4; j++) {
            __nv_bfloat162 p = __floats2bfloat162_rn(v[i*8 + 2*j] * inv, v[i*8 + 2*j + 1] * inv);
            w[j] = *(uint32_t*)&p;
        }
        dst[t + i*256] = u;
    }
}

// ---------------- kernel 7: output  out = gamma * (V A^T) + x ----------------
__global__ void __launch_bounds__(256, 2) k_gemm_o(const float* __restrict__ xin,
                                                   const float* __restrict__ gma,
                                                   float* __restrict__ out) {
    const int b = blockIdx.z, m0 = blockIdx.y * BM, n0 = blockIdx.x * BN;
    float acc[2][8][4] = {};
    gemm_pipe(&g_V[b][m0][0], NDIM, &g_A[b][n0][0], NDIM, NDIM / BK, acc);

    const float gm = gma[0];
    const int lane = threadIdx.x & 31, warp = threadIdx.x >> 5;
    const int wm = warp >> 1, wn = warp & 1, r = lane >> 2, q = lane & 3;
    #pragma unroll
    for (int mi = 0; mi < 2; mi++)
        #pragma unroll
        for (int ni = 0; ni < 8; ni++) {
            const int m = m0 + wm*32 + mi*16 + r;
            const int n = n0 + wn*64 + ni*8 + 2*q;
            const size_t i0 = ((size_t)(b*CDIM + m)) * NDIM + n;
            const size_t i8 = i0 + (size_t)8 * NDIM;
            float2 x0 = *(const float2*)&xin[i0];
            float2 x8 = *(const float2*)&xin[i8];
            *(float2*)&out[i0] = make_float2(gm * acc[mi][ni][0] + x0.x, gm * acc[mi][ni][1] + x0.y);
            *(float2*)&out[i8] = make_float2(gm * acc[mi][ni][2] + x8.x, gm * acc[mi][ni][3] + x8.y);
        }
}

// ---------------- launch ----------------
extern "C" void kernel_launch(void* const* d_in, const int* in_sizes, int n_in,
                              void* d_out, int out_size) {
    const float* x  = (const float*)d_in[0];
    // d_in[1] = s (unused by the reference)
    const float* wq = (const float*)d_in[2];
    const float* bq = (const float*)d_in[3];
    const float* wk = (const float*)d_in[4];
    const float* bk = (const float*)d_in[5];
    const float* wv = (const float*)d_in[6];
    const float* bv = (const float*)d_in[7];
    const float* gm = (const float*)d_in[8];
    float* out = (float*)d_out;

    cudaFuncSetAttribute(k_gemm_qk, cudaFuncAttributeMaxDynamicSharedMemorySize, SMEM_BYTES);
    cudaFuncSetAttribute(k_gemm_v,  cudaFuncAttributeMaxDynamicSharedMemorySize, SMEM_BYTES);
    cudaFuncSetAttribute(k_gemm_s,  cudaFuncAttributeMaxDynamicSharedMemorySize, SMEM_BYTES);
    cudaFuncSetAttribute(k_gemm_o,  cudaFuncAttributeMaxDynamicSharedMemorySize, SMEM_BYTES);

    k_convert_x<<<dim3(128, 16, 2), dim3(32, 8)>>>(x);
    k_convert_w<<<1281, 256>>>(wq, wk, wv, bq, bk);
    k_gemm_qk<<<dim3(1, 32, 2),  256, SMEM_BYTES>>>();
    k_gemm_v <<<dim3(32, 4, 2),  256, SMEM_BYTES>>>(bv);
    k_gemm_s <<<dim3(32, 32, 2), 256, SMEM_BYTES>>>();
    k_softmax<<<8192, 256>>>();
    k_gemm_o <<<dim3(32, 4, 2),  256, SMEM_BYTES>>>(x, gm, out);
}

// round 7
// speedup vs baseline: 1.8801x; 1.0285x over previous
#include <cuda_runtime.h>
#include <cuda_bf16.h>
#include <cstdint>

#define BATCH 2
#define CDIM  512
#define CQK   64
#define NDIM  4096

// shared mma.sync GEMM tile config (projections + S): BM=BN=128, BK=64, 256 threads
#define BM  128
#define BN  128
#define BK  64
#define ROWB 128                    // bytes per smem row (BK * 2, swizzled)
#define A_BYTES (BM * ROWB)         // 16384
#define STAGE_B (A_BYTES + BN*ROWB) // 32768 bytes per stage
#define STAGES 3
#define SMEM_BYTES (STAGES * STAGE_B)  // 98304

// O-GEMM config: BM2=256 x BN2=128, 8 warps at 64x64 warp tiles, 1 CTA/SM
#define OBM 256
#define O_A_BYTES (OBM * ROWB)         // 32768
#define O_STAGE_B (O_A_BYTES + BN*ROWB) // 49152
#define O_SMEM (STAGES * O_STAGE_B)     // 147456

// ---------------- scratch (device globals; no allocation allowed) ----------------
__device__ __nv_bfloat16 g_Xt[BATCH][NDIM][CDIM];    // x transposed, bf16
__device__ __nv_bfloat16 g_Wqk[2*CQK][CDIM];         // [wq; wk] bf16
__device__ float         g_bqk[2*CQK];               // [bq; bk]
__device__ __nv_bfloat16 g_Wv[CDIM][CDIM];           // wv bf16
__device__ __nv_bfloat16 g_QK[BATCH][NDIM][2*CQK];   // q|k per token
__device__ __nv_bfloat16 g_V[BATCH][CDIM][NDIM];     // v in [c][n] layout
__device__ __nv_bfloat16 g_A[BATCH][NDIM][NDIM];     // E = exp(S), unnormalized, bf16
__device__ float         g_psum[BATCH][32][NDIM];    // per-column-tile partial row sums
__device__ float         g_rsum[BATCH][NDIM];        // full row sums

// ---------------- PTX helpers ----------------
__device__ __forceinline__ uint32_t smem_u32(const void* p) {
    return (uint32_t)__cvta_generic_to_shared(p);
}
__device__ __forceinline__ void cp16(uint32_t dst, const void* src) {
    asm volatile("cp.async.cg.shared.global [%0], [%1], 16;\n" :: "r"(dst), "l"(src));
}
__device__ __forceinline__ void cp_commit() { asm volatile("cp.async.commit_group;\n"); }
template<int N> __device__ __forceinline__ void cp_wait() {
    asm volatile("cp.async.wait_group %0;\n" :: "n"(N));
}
__device__ __forceinline__ void ldsm4(uint32_t r[4], uint32_t addr) {
    asm volatile("ldmatrix.sync.aligned.m8n8.x4.shared.b16 {%0,%1,%2,%3}, [%4];\n"
                 : "=r"(r[0]), "=r"(r[1]), "=r"(r[2]), "=r"(r[3]) : "r"(addr));
}
__device__ __forceinline__ void mma16816(float c[4], const uint32_t a[4], const uint32_t b[2]) {
    asm volatile(
        "mma.sync.aligned.m16n8k16.row.col.f32.bf16.bf16.f32 "
        "{%0,%1,%2,%3}, {%4,%5,%6,%7}, {%8,%9}, {%0,%1,%2,%3};\n"
        : "+f"(c[0]), "+f"(c[1]), "+f"(c[2]), "+f"(c[3])
        : "r"(a[0]), "r"(a[1]), "r"(a[2]), "r"(a[3]), "r"(b[0]), "r"(b[1]));
}
__device__ __forceinline__ uint32_t swz(uint32_t off) {
    return off ^ ((off >> 3) & 0x70);
}

// ---------------- 3-stage pipelined GEMM (128x128): C += A[BM,K] * B[BN,K]^T ----------------
__device__ __forceinline__ void gemm_pipe(
    const __nv_bfloat16* __restrict__ Ag, int lda,
    const __nv_bfloat16* __restrict__ Bg, int ldb,
    int Ktiles, float (&acc)[2][8][4])
{
    extern __shared__ __align__(1024) char smem[];
    const uint32_t sbase = smem_u32(smem);
    const int tid  = threadIdx.x;
    const int lane = tid & 31, warp = tid >> 5;
    const int wm = warp >> 1, wn = warp & 1;
    const int lrow = tid >> 3;
    const int lcol = (tid & 7) * 16;

    const int a_r = (lane & 7) + (((lane >> 3) & 1) << 3);
    const int a_c = ((lane >> 4) << 3) * 2;
    const int b_r = (lane & 7) + ((lane >> 4) << 3);
    const int b_c = (((lane >> 3) & 1) << 3) * 2;

    auto load_tile = [&](int stage, int kt) {
        const uint32_t as = sbase + stage * STAGE_B;
        const uint32_t bs = as + A_BYTES;
        const __nv_bfloat16* a = Ag + (size_t)kt * BK;
        const __nv_bfloat16* b = Bg + (size_t)kt * BK;
        #pragma unroll
        for (int i = 0; i < 4; i++) {
            const int r = lrow + i*32;
            cp16(as + swz(r*ROWB + lcol), (const char*)(a + (size_t)r * lda) + lcol);
        }
        #pragma unroll
        for (int i = 0; i < 4; i++) {
            const int r = lrow + i*32;
            cp16(bs + swz(r*ROWB + lcol), (const char*)(b + (size_t)r * ldb) + lcol);
        }
        cp_commit();
    };

    load_tile(0, 0);
    if (Ktiles > 1) load_tile(1, 1);

    for (int kt = 0; kt < Ktiles; kt++) {
        if (kt + 2 <= Ktiles) cp_wait<1>(); else cp_wait<0>();
        __syncthreads();
        if (kt + 2 < Ktiles) load_tile((kt + 2) % STAGES, kt + 2);

        const uint32_t as = sbase + (kt % STAGES) * STAGE_B;
        const uint32_t bs = as + A_BYTES;

        #pragma unroll
        for (int kk = 0; kk < BK; kk += 16) {
            uint32_t af[2][4];
            #pragma unroll
            for (int mi = 0; mi < 2; mi++) {
                const int row = wm*32 + mi*16 + a_r;
                ldsm4(af[mi], as + swz(row*ROWB + kk*2 + a_c));
            }
            uint32_t bfr[4][4];
            #pragma unroll
            for (int nj = 0; nj < 4; nj++) {
                const int row = wn*64 + nj*16 + b_r;
                ldsm4(bfr[nj], bs + swz(row*ROWB + kk*2 + b_c));
            }
            #pragma unroll
            for (int mi = 0; mi < 2; mi++)
                #pragma unroll
                for (int nj = 0; nj < 4; nj++) {
                    mma16816(acc[mi][2*nj  ], af[mi], &bfr[nj][0]);
                    mma16816(acc[mi][2*nj+1], af[mi], &bfr[nj][2]);
                }
        }
    }
}

// ---------------- kernel 1: transpose+convert x -> Xt bf16 ----------------
__global__ void k_convert_x(const float* __restrict__ x) {
    __shared__ float tile[32][33];
    const int b  = blockIdx.z;
    const int n0 = blockIdx.x * 32, c0 = blockIdx.y * 32;
    const int tx = threadIdx.x, ty = threadIdx.y;   // (32, 8)
    #pragma unroll
    for (int i = 0; i < 32; i += 8)
        tile[ty + i][tx] = x[((size_t)(b*CDIM + c0 + ty + i)) * NDIM + n0 + tx];
    __syncthreads();
    #pragma unroll
    for (int i = 0; i < 32; i += 8)
        g_Xt[b][n0 + ty + i][c0 + tx] = __float2bfloat16(tile[tx][ty + i]);
}

// ---------------- kernel 2: convert weights/biases ----------------
__global__ void k_convert_w(const float* __restrict__ wq, const float* __restrict__ wk,
                            const float* __restrict__ wv,
                            const float* __restrict__ bq, const float* __restrict__ bk) {
    const int idx = blockIdx.x * 256 + threadIdx.x;
    if (idx < 32768) {
        ((__nv_bfloat16*)g_Wqk)[idx] = __float2bfloat16(wq[idx]);
    } else if (idx < 65536) {
        ((__nv_bfloat16*)g_Wqk)[idx] = __float2bfloat16(wk[idx - 32768]);
    } else if (idx < 65536 + 262144) {
        ((__nv_bfloat16*)g_Wv)[idx - 65536] = __float2bfloat16(wv[idx - 65536]);
    } else if (idx < 65536 + 262144 + 64) {
        g_bqk[idx - 327680] = bq[idx - 327680];
    } else if (idx < 65536 + 262144 + 128) {
        g_bqk[idx - 327680] = bk[idx - 327680 - 64];
    }
}

// ---------------- kernel 3: QK projection ----------------
__global__ void __launch_bounds__(256, 2) k_gemm_qk() {
    const int b = blockIdx.z, m0 = blockIdx.y * BM;
    float acc[2][8][4] = {};
    gemm_pipe(&g_Xt[b][m0][0], CDIM, &g_Wqk[0][0], CDIM, CDIM / BK, acc);

    const int lane = threadIdx.x & 31, warp = threadIdx.x >> 5;
    const int wm = warp >> 1, wn = warp & 1, r = lane >> 2, q = lane & 3;
    #pragma unroll
    for (int mi = 0; mi < 2; mi++)
        #pragma unroll
        for (int ni = 0; ni < 8; ni++) {
            const int m = m0 + wm*32 + mi*16 + r;
            const int n = wn*64 + ni*8 + 2*q;
            const float b0 = g_bqk[n], b1 = g_bqk[n + 1];
            *(__nv_bfloat162*)&g_QK[b][m    ][n] = __floats2bfloat162_rn(acc[mi][ni][0] + b0, acc[mi][ni][1] + b1);
            *(__nv_bfloat162*)&g_QK[b][m + 8][n] = __floats2bfloat162_rn(acc[mi][ni][2] + b0, acc[mi][ni][3] + b1);
        }
}

// ---------------- kernel 4: V projection ----------------
__global__ void __launch_bounds__(256, 2) k_gemm_v(const float* __restrict__ bv) {
    const int b = blockIdx.z, m0 = blockIdx.y * BM, n0 = blockIdx.x * BN;
    float acc[2][8][4] = {};
    gemm_pipe(&g_Wv[m0][0], CDIM, &g_Xt[b][n0][0], CDIM, CDIM / BK, acc);

    const int lane = threadIdx.x & 31, warp = threadIdx.x >> 5;
    const int wm = warp >> 1, wn = warp & 1, r = lane >> 2, q = lane & 3;
    #pragma unroll
    for (int mi = 0; mi < 2; mi++) {
        const int m = m0 + wm*32 + mi*16 + r;
        const float bm0 = bv[m], bm8 = bv[m + 8];
        #pragma unroll
        for (int ni = 0; ni < 8; ni++) {
            const int n = n0 + wn*64 + ni*8 + 2*q;
            *(__nv_bfloat162*)&g_V[b][m    ][n] = __floats2bfloat162_rn(acc[mi][ni][0] + bm0, acc[mi][ni][1] + bm0);
            *(__nv_bfloat162*)&g_V[b][m + 8][n] = __floats2bfloat162_rn(acc[mi][ni][2] + bm8, acc[mi][ni][3] + bm8);
        }
    }
}

// ---------------- kernel 5: E = exp(Q K^T), unnormalized, + partial row sums ----------------
__global__ void __launch_bounds__(256, 2) k_gemm_s() {
    const int b = blockIdx.z, m0 = blockIdx.y * BM, n0 = blockIdx.x * BN;
    float acc[2][8][4] = {};
    gemm_pipe(&g_QK[b][m0][0], 2*CQK, &g_QK[b][n0][CQK], 2*CQK, 1, acc);

    __shared__ float s_part[2][BM];
    const int lane = threadIdx.x & 31, warp = threadIdx.x >> 5;
    const int wm = warp >> 1, wn = warp & 1, r = lane >> 2, q = lane & 3;

    float rsum[2][2] = {};
    #pragma unroll
    for (int mi = 0; mi < 2; mi++)
        #pragma unroll
        for (int ni = 0; ni < 8; ni++) {
            const int m = m0 + wm*32 + mi*16 + r;
            const int n = n0 + wn*64 + ni*8 + 2*q;
            const float e0 = __expf(acc[mi][ni][0]);
            const float e1 = __expf(acc[mi][ni][1]);
            const float e2 = __expf(acc[mi][ni][2]);
            const float e3 = __expf(acc[mi][ni][3]);
            *(__nv_bfloat162*)&g_A[b][m    ][n] = __floats2bfloat162_rn(e0, e1);
            *(__nv_bfloat162*)&g_A[b][m + 8][n] = __floats2bfloat162_rn(e2, e3);
            rsum[mi][0] += e0 + e1;
            rsum[mi][1] += e2 + e3;
        }
    // reduce over q (lanes sharing a row): xor 1, 2
    #pragma unroll
    for (int mi = 0; mi < 2; mi++)
        #pragma unroll
        for (int h = 0; h < 2; h++) {
            rsum[mi][h] += __shfl_xor_sync(0xffffffffu, rsum[mi][h], 1);
            rsum[mi][h] += __shfl_xor_sync(0xffffffffu, rsum[mi][h], 2);
        }
    if (q == 0) {
        #pragma unroll
        for (int mi = 0; mi < 2; mi++)
            #pragma unroll
            for (int h = 0; h < 2; h++)
                s_part[wn][wm*32 + mi*16 + h*8 + r] = rsum[mi][h];
    }
    __syncthreads();
    if (threadIdx.x < BM)
        g_psum[b][blockIdx.x][m0 + threadIdx.x] = s_part[0][threadIdx.x] + s_part[1][threadIdx.x];
}

// ---------------- kernel 5b: fold partial row sums (deterministic order) ----------------
__global__ void k_rowsum() {
    const int id = blockIdx.x * 256 + threadIdx.x;   // 0..8191
    const int b = id / NDIM, m = id % NDIM;
    float s = 0.f;
    #pragma unroll
    for (int t = 0; t < 32; t++) s += g_psum[b][t][m];
    g_rsum[b][m] = s;
}

// ---------------- kernel 6: O-GEMM (256x128 tile)  out = (gamma/rowsum_n) * (V E^T) + x ----------------
__global__ void __launch_bounds__(256, 1) k_gemm_o(const float* __restrict__ xin,
                                                   const float* __restrict__ gma,
                                                   float* __restrict__ out) {
    extern __shared__ __align__(1024) char smem[];
    const uint32_t sbase = smem_u32(smem);
    const int tid  = threadIdx.x;
    const int lane = tid & 31, warp = tid >> 5;
    const int wm = warp >> 1, wn = warp & 1;          // 4m x 2n, warp tile 64x64
    const int b = blockIdx.z, m0 = blockIdx.y * OBM, n0 = blockIdx.x * BN;
    const int Kt = NDIM / BK;                         // 64

    const __nv_bfloat16* Vg = &g_V[b][m0][0];
    const __nv_bfloat16* Eg = &g_A[b][n0][0];

    const int lrow = tid >> 3;
    const int lcol = (tid & 7) * 16;
    const int a_r = (lane & 7) + (((lane >> 3) & 1) << 3);
    const int a_c = ((lane >> 4) << 3) * 2;
    const int b_r = (lane & 7) + ((lane >> 4) << 3);
    const int b_c = (((lane >> 3) & 1) << 3) * 2;

    auto load_tile = [&](int stage, int kt) {
        const uint32_t vs = sbase + stage * O_STAGE_B;
        const uint32_t es = vs + O_A_BYTES;
        const __nv_bfloat16* v = Vg + (size_t)kt * BK;
        const __nv_bfloat16* e = Eg + (size_t)kt * BK;
        #pragma unroll
        for (int i = 0; i < 8; i++) {
            const int r = lrow + i*32;
            cp16(vs + swz(r*ROWB + lcol), (const char*)(v + (size_t)r * NDIM) + lcol);
        }
        #pragma unroll
        for (int i = 0; i < 4; i++) {
            const int r = lrow + i*32;
            cp16(es + swz(r*ROWB + lcol), (const char*)(e + (size_t)r * NDIM) + lcol);
        }
        cp_commit();
    };

    float acc[4][8][4] = {};
    load_tile(0, 0);
    load_tile(1, 1);

    for (int kt = 0; kt < Kt; kt++) {
        if (kt + 2 <= Kt) cp_wait<1>(); else cp_wait<0>();
        __syncthreads();
        if (kt + 2 < Kt) load_tile((kt + 2) % STAGES, kt + 2);

        const uint32_t vs = sbase + (kt % STAGES) * O_STAGE_B;
        const uint32_t es = vs + O_A_BYTES;

        #pragma unroll
        for (int kk = 0; kk < BK; kk += 16) {
            uint32_t af[4][4];
            #pragma unroll
            for (int mi = 0; mi < 4; mi++) {
                const int row = wm*64 + mi*16 + a_r;
                ldsm4(af[mi], vs + swz(row*ROWB + kk*2 + a_c));
            }
            uint32_t bfr[4][4];
            #pragma unroll
            for (int nj = 0; nj < 4; nj++) {
                const int row = wn*64 + nj*16 + b_r;
                ldsm4(bfr[nj], es + swz(row*ROWB + kk*2 + b_c));
            }
            #pragma unroll
            for (int mi = 0; mi < 4; mi++)
                #pragma unroll
                for (int nj = 0; nj < 4; nj++) {
                    mma16816(acc[mi][2*nj  ], af[mi], &bfr[nj][0]);
                    mma16816(acc[mi][2*nj+1], af[mi], &bfr[nj][2]);
                }
        }
    }

    const float gm = gma[0];
    const int r = lane >> 2, q = lane & 3;
    #pragma unroll
    for (int ni = 0; ni < 8; ni++) {
        const int n = n0 + wn*64 + ni*8 + 2*q;
        const float sc0 = gm / g_rsum[b][n];
        const float sc1 = gm / g_rsum[b][n + 1];
        #pragma unroll
        for (int mi = 0; mi < 4; mi++) {
            const int m = m0 + wm*64 + mi*16 + r;
            const size_t i0 = ((size_t)(b*CDIM + m)) * NDIM + n;
            const size_t i8 = i0 + (size_t)8 * NDIM;
            float2 x0 = *(const float2*)&xin[i0];
            float2 x8 = *(const float2*)&xin[i8];
            *(float2*)&out[i0] = make_float2(sc0 * acc[mi][ni][0] + x0.x, sc1 * acc[mi][ni][1] + x0.y);
            *(float2*)&out[i8] = make_float2(sc0 * acc[mi][ni][2] + x8.x, sc1 * acc[mi][ni][3] + x8.y);
        }
    }
}

// ---------------- launch ----------------
extern "C" void kernel_launch(void* const* d_in, const int* in_sizes, int n_in,
                              void* d_out, int out_size) {
    const float* x  = (const float*)d_in[0];
    // d_in[1] = s (unused by the reference)
    const float* wq = (const float*)d_in[2];
    const float* bq = (const float*)d_in[3];
    const float* wk = (const float*)d_in[4];
    const float* bk = (const float*)d_in[5];
    const float* wv = (const float*)d_in[6];
    const float* bv = (const float*)d_in[7];
    const float* gm = (const float*)d_in[8];
    float* out = (float*)d_out;

    cudaFuncSetAttribute(k_gemm_qk, cudaFuncAttributeMaxDynamicSharedMemorySize, SMEM_BYTES);
    cudaFuncSetAttribute(k_gemm_v,  cudaFuncAttributeMaxDynamicSharedMemorySize, SMEM_BYTES);
    cudaFuncSetAttribute(k_gemm_s,  cudaFuncAttributeMaxDynamicSharedMemorySize, SMEM_BYTES);
    cudaFuncSetAttribute(k_gemm_o,  cudaFuncAttributeMaxDynamicSharedMemorySize, O_SMEM);

    k_convert_x<<<dim3(128, 16, 2), dim3(32, 8)>>>(x);
    k_convert_w<<<1281, 256>>>(wq, wk, wv, bq, bk);
    k_gemm_qk<<<dim3(1, 32, 2),  256, SMEM_BYTES>>>();
    k_gemm_v <<<dim3(32, 4, 2),  256, SMEM_BYTES>>>(bv);
    k_gemm_s <<<dim3(32, 32, 2), 256, SMEM_BYTES>>>();
    k_rowsum <<<32, 256>>>();
    k_gemm_o <<<dim3(32, 2, 2),  256, O_SMEM>>>(x, gm, out);
}

// round 8
// speedup vs baseline: 1.9540x; 1.0393x over previous
#include <cuda_runtime.h>
#include <cuda_bf16.h>
#include <cstdint>

#define BATCH 2
#define CDIM  512
#define CQK   64
#define NDIM  4096

// shared mma.sync GEMM tile config (projections + S): BM=BN=128, BK=64, 256 threads
#define BM  128
#define BN  128
#define BK  64
#define ROWB 128                    // bytes per smem row (BK * 2, swizzled)
#define A_BYTES (BM * ROWB)         // 16384
#define STAGE_B (A_BYTES + BN*ROWB) // 32768 bytes per stage
#define STAGES 3
#define SMEM_BYTES (STAGES * STAGE_B)  // 98304

// O-GEMM config: BM2=256 x BN2=128, 8 warps at 64x64 warp tiles, 1 CTA/SM, 4-stage pipe
#define OBM 256
#define O_A_BYTES (OBM * ROWB)          // 32768
#define O_STAGE_B (O_A_BYTES + BN*ROWB) // 49152
#define O_STAGES 4
#define O_SMEM (O_STAGES * O_STAGE_B)   // 196608

// ---------------- scratch (device globals; no allocation allowed) ----------------
__device__ __nv_bfloat16 g_Xt[BATCH][NDIM][CDIM];    // x transposed, bf16
__device__ __nv_bfloat16 g_Wqk[2*CQK][CDIM];         // [wq; wk] bf16
__device__ float         g_bqk[2*CQK];               // [bq; bk]
__device__ __nv_bfloat16 g_Wv[CDIM][CDIM];           // wv bf16
__device__ __nv_bfloat16 g_QK[BATCH][NDIM][2*CQK];   // q|k per token
__device__ __nv_bfloat16 g_V[BATCH][CDIM][NDIM];     // v in [c][n] layout
__device__ __nv_bfloat16 g_A[BATCH][NDIM][NDIM];     // E = exp(S), unnormalized, bf16
__device__ float         g_psum[BATCH][32][NDIM];    // per-column-tile partial row sums
__device__ float         g_rsum[BATCH][NDIM];        // reciprocal of full row sums

// ---------------- PTX helpers ----------------
__device__ __forceinline__ uint32_t smem_u32(const void* p) {
    return (uint32_t)__cvta_generic_to_shared(p);
}
__device__ __forceinline__ void cp16(uint32_t dst, const void* src) {
    asm volatile("cp.async.cg.shared.global [%0], [%1], 16;\n" :: "r"(dst), "l"(src));
}
__device__ __forceinline__ void cp_commit() { asm volatile("cp.async.commit_group;\n"); }
template<int N> __device__ __forceinline__ void cp_wait() {
    asm volatile("cp.async.wait_group %0;\n" :: "n"(N));
}
__device__ __forceinline__ void ldsm4(uint32_t r[4], uint32_t addr) {
    asm volatile("ldmatrix.sync.aligned.m8n8.x4.shared.b16 {%0,%1,%2,%3}, [%4];\n"
                 : "=r"(r[0]), "=r"(r[1]), "=r"(r[2]), "=r"(r[3]) : "r"(addr));
}
__device__ __forceinline__ void mma16816(float c[4], const uint32_t a[4], const uint32_t b[2]) {
    asm volatile(
        "mma.sync.aligned.m16n8k16.row.col.f32.bf16.bf16.f32 "
        "{%0,%1,%2,%3}, {%4,%5,%6,%7}, {%8,%9}, {%0,%1,%2,%3};\n"
        : "+f"(c[0]), "+f"(c[1]), "+f"(c[2]), "+f"(c[3])
        : "r"(a[0]), "r"(a[1]), "r"(a[2]), "r"(a[3]), "r"(b[0]), "r"(b[1]));
}
__device__ __forceinline__ uint32_t swz(uint32_t off) {
    return off ^ ((off >> 3) & 0x70);
}

// ---------------- 3-stage pipelined GEMM (128x128): C += A[BM,K] * B[BN,K]^T ----------------
__device__ __forceinline__ void gemm_pipe(
    const __nv_bfloat16* __restrict__ Ag, int lda,
    const __nv_bfloat16* __restrict__ Bg, int ldb,
    int Ktiles, float (&acc)[2][8][4])
{
    extern __shared__ __align__(1024) char smem[];
    const uint32_t sbase = smem_u32(smem);
    const int tid  = threadIdx.x;
    const int lane = tid & 31, warp = tid >> 5;
    const int wm = warp >> 1, wn = warp & 1;
    const int lrow = tid >> 3;
    const int lcol = (tid & 7) * 16;

    const int a_r = (lane & 7) + (((lane >> 3) & 1) << 3);
    const int a_c = ((lane >> 4) << 3) * 2;
    const int b_r = (lane & 7) + ((lane >> 4) << 3);
    const int b_c = (((lane >> 3) & 1) << 3) * 2;

    auto load_tile = [&](int stage, int kt) {
        const uint32_t as = sbase + stage * STAGE_B;
        const uint32_t bs = as + A_BYTES;
        const __nv_bfloat16* a = Ag + (size_t)kt * BK;
        const __nv_bfloat16* b = Bg + (size_t)kt * BK;
        #pragma unroll
        for (int i = 0; i < 4; i++) {
            const int r = lrow + i*32;
            cp16(as + swz(r*ROWB + lcol), (const char*)(a + (size_t)r * lda) + lcol);
        }
        #pragma unroll
        for (int i = 0; i < 4; i++) {
            const int r = lrow + i*32;
            cp16(bs + swz(r*ROWB + lcol), (const char*)(b + (size_t)r * ldb) + lcol);
        }
        cp_commit();
    };

    load_tile(0, 0);
    if (Ktiles > 1) load_tile(1, 1);

    for (int kt = 0; kt < Ktiles; kt++) {
        if (kt + 2 <= Ktiles) cp_wait<1>(); else cp_wait<0>();
        __syncthreads();
        if (kt + 2 < Ktiles) load_tile((kt + 2) % STAGES, kt + 2);

        const uint32_t as = sbase + (kt % STAGES) * STAGE_B;
        const uint32_t bs = as + A_BYTES;

        #pragma unroll
        for (int kk = 0; kk < BK; kk += 16) {
            uint32_t af[2][4];
            #pragma unroll
            for (int mi = 0; mi < 2; mi++) {
                const int row = wm*32 + mi*16 + a_r;
                ldsm4(af[mi], as + swz(row*ROWB + kk*2 + a_c));
            }
            uint32_t bfr[4][4];
            #pragma unroll
            for (int nj = 0; nj < 4; nj++) {
                const int row = wn*64 + nj*16 + b_r;
                ldsm4(bfr[nj], bs + swz(row*ROWB + kk*2 + b_c));
            }
            #pragma unroll
            for (int mi = 0; mi < 2; mi++)
                #pragma unroll
                for (int nj = 0; nj < 4; nj++) {
                    mma16816(acc[mi][2*nj  ], af[mi], &bfr[nj][0]);
                    mma16816(acc[mi][2*nj+1], af[mi], &bfr[nj][2]);
                }
        }
    }
}

// ---------------- kernel 1: transpose+convert x -> Xt bf16 ----------------
__global__ void k_convert_x(const float* __restrict__ x) {
    __shared__ float tile[32][33];
    const int b  = blockIdx.z;
    const int n0 = blockIdx.x * 32, c0 = blockIdx.y * 32;
    const int tx = threadIdx.x, ty = threadIdx.y;   // (32, 8)
    #pragma unroll
    for (int i = 0; i < 32; i += 8)
        tile[ty + i][tx] = x[((size_t)(b*CDIM + c0 + ty + i)) * NDIM + n0 + tx];
    __syncthreads();
    #pragma unroll
    for (int i = 0; i < 32; i += 8)
        g_Xt[b][n0 + ty + i][c0 + tx] = __float2bfloat16(tile[tx][ty + i]);
}

// ---------------- kernel 2: convert weights/biases ----------------
__global__ void k_convert_w(const float* __restrict__ wq, const float* __restrict__ wk,
                            const float* __restrict__ wv,
                            const float* __restrict__ bq, const float* __restrict__ bk) {
    const int idx = blockIdx.x * 256 + threadIdx.x;
    if (idx < 32768) {
        ((__nv_bfloat16*)g_Wqk)[idx] = __float2bfloat16(wq[idx]);
    } else if (idx < 65536) {
        ((__nv_bfloat16*)g_Wqk)[idx] = __float2bfloat16(wk[idx - 32768]);
    } else if (idx < 65536 + 262144) {
        ((__nv_bfloat16*)g_Wv)[idx - 65536] = __float2bfloat16(wv[idx - 65536]);
    } else if (idx < 65536 + 262144 + 64) {
        g_bqk[idx - 327680] = bq[idx - 327680];
    } else if (idx < 65536 + 262144 + 128) {
        g_bqk[idx - 327680] = bk[idx - 327680 - 64];
    }
}

// ---------------- kernel 3: QK projection ----------------
__global__ void __launch_bounds__(256, 2) k_gemm_qk() {
    const int b = blockIdx.z, m0 = blockIdx.y * BM;
    float acc[2][8][4] = {};
    gemm_pipe(&g_Xt[b][m0][0], CDIM, &g_Wqk[0][0], CDIM, CDIM / BK, acc);

    const int lane = threadIdx.x & 31, warp = threadIdx.x >> 5;
    const int wm = warp >> 1, wn = warp & 1, r = lane >> 2, q = lane & 3;
    #pragma unroll
    for (int mi = 0; mi < 2; mi++)
        #pragma unroll
        for (int ni = 0; ni < 8; ni++) {
            const int m = m0 + wm*32 + mi*16 + r;
            const int n = wn*64 + ni*8 + 2*q;
            const float b0 = g_bqk[n], b1 = g_bqk[n + 1];
            *(__nv_bfloat162*)&g_QK[b][m    ][n] = __floats2bfloat162_rn(acc[mi][ni][0] + b0, acc[mi][ni][1] + b1);
            *(__nv_bfloat162*)&g_QK[b][m + 8][n] = __floats2bfloat162_rn(acc[mi][ni][2] + b0, acc[mi][ni][3] + b1);
        }
}

// ---------------- kernel 4: V projection ----------------
__global__ void __launch_bounds__(256, 2) k_gemm_v(const float* __restrict__ bv) {
    const int b = blockIdx.z, m0 = blockIdx.y * BM, n0 = blockIdx.x * BN;
    float acc[2][8][4] = {};
    gemm_pipe(&g_Wv[m0][0], CDIM, &g_Xt[b][n0][0], CDIM, CDIM / BK, acc);

    const int lane = threadIdx.x & 31, warp = threadIdx.x >> 5;
    const int wm = warp >> 1, wn = warp & 1, r = lane >> 2, q = lane & 3;
    #pragma unroll
    for (int mi = 0; mi < 2; mi++) {
        const int m = m0 + wm*32 + mi*16 + r;
        const float bm0 = bv[m], bm8 = bv[m + 8];
        #pragma unroll
        for (int ni = 0; ni < 8; ni++) {
            const int n = n0 + wn*64 + ni*8 + 2*q;
            *(__nv_bfloat162*)&g_V[b][m    ][n] = __floats2bfloat162_rn(acc[mi][ni][0] + bm0, acc[mi][ni][1] + bm0);
            *(__nv_bfloat162*)&g_V[b][m + 8][n] = __floats2bfloat162_rn(acc[mi][ni][2] + bm8, acc[mi][ni][3] + bm8);
        }
    }
}

// ---------------- kernel 5: E = exp(Q K^T), unnormalized, + partial row sums ----------------
__global__ void __launch_bounds__(256, 2) k_gemm_s() {
    const int b = blockIdx.z, m0 = blockIdx.y * BM, n0 = blockIdx.x * BN;
    float acc[2][8][4] = {};
    gemm_pipe(&g_QK[b][m0][0], 2*CQK, &g_QK[b][n0][CQK], 2*CQK, 1, acc);

    __shared__ float s_part[2][BM];
    const int lane = threadIdx.x & 31, warp = threadIdx.x >> 5;
    const int wm = warp >> 1, wn = warp & 1, r = lane >> 2, q = lane & 3;

    float rsum[2][2] = {};
    #pragma unroll
    for (int mi = 0; mi < 2; mi++)
        #pragma unroll
        for (int ni = 0; ni < 8; ni++) {
            const int m = m0 + wm*32 + mi*16 + r;
            const int n = n0 + wn*64 + ni*8 + 2*q;
            const float e0 = __expf(acc[mi][ni][0]);
            const float e1 = __expf(acc[mi][ni][1]);
            const float e2 = __expf(acc[mi][ni][2]);
            const float e3 = __expf(acc[mi][ni][3]);
            *(__nv_bfloat162*)&g_A[b][m    ][n] = __floats2bfloat162_rn(e0, e1);
            *(__nv_bfloat162*)&g_A[b][m + 8][n] = __floats2bfloat162_rn(e2, e3);
            rsum[mi][0] += e0 + e1;
            rsum[mi][1] += e2 + e3;
        }
    #pragma unroll
    for (int mi = 0; mi < 2; mi++)
        #pragma unroll
        for (int h = 0; h < 2; h++) {
            rsum[mi][h] += __shfl_xor_sync(0xffffffffu, rsum[mi][h], 1);
            rsum[mi][h] += __shfl_xor_sync(0xffffffffu, rsum[mi][h], 2);
        }
    if (q == 0) {
        #pragma unroll
        for (int mi = 0; mi < 2; mi++)
            #pragma unroll
            for (int h = 0; h < 2; h++)
                s_part[wn][wm*32 + mi*16 + h*8 + r] = rsum[mi][h];
    }
    __syncthreads();
    if (threadIdx.x < BM)
        g_psum[b][blockIdx.x][m0 + threadIdx.x] = s_part[0][threadIdx.x] + s_part[1][threadIdx.x];
}

// ---------------- kernel 5b: fold partial row sums -> reciprocal ----------------
__global__ void k_rowsum() {
    const int id = blockIdx.x * 256 + threadIdx.x;   // 0..8191
    const int b = id / NDIM, m = id % NDIM;
    float s = 0.f;
    #pragma unroll
    for (int t = 0; t < 32; t++) s += g_psum[b][t][m];
    g_rsum[b][m] = 1.0f / s;
}

// ---------------- kernel 6: O-GEMM (256x128, 4-stage)  out = gamma*rinv_n*(V E^T) + x ----------------
__global__ void __launch_bounds__(256, 1) k_gemm_o(const float* __restrict__ xin,
                                                   const float* __restrict__ gma,
                                                   float* __restrict__ out) {
    extern __shared__ __align__(1024) char smem[];
    const uint32_t sbase = smem_u32(smem);
    const int tid  = threadIdx.x;
    const int lane = tid & 31, warp = tid >> 5;
    const int wm = warp >> 1, wn = warp & 1;          // 4m x 2n, warp tile 64x64
    const int b = blockIdx.z, m0 = blockIdx.y * OBM, n0 = blockIdx.x * BN;
    const int Kt = NDIM / BK;                         // 64

    const __nv_bfloat16* Vg = &g_V[b][m0][0];
    const __nv_bfloat16* Eg = &g_A[b][n0][0];

    const int lrow = tid >> 3;
    const int lcol = (tid & 7) * 16;
    const int a_r = (lane & 7) + (((lane >> 3) & 1) << 3);
    const int a_c = ((lane >> 4) << 3) * 2;
    const int b_r = (lane & 7) + ((lane >> 4) << 3);
    const int b_c = (((lane >> 3) & 1) << 3) * 2;

    auto load_tile = [&](int stage, int kt) {
        const uint32_t vs = sbase + stage * O_STAGE_B;
        const uint32_t es = vs + O_A_BYTES;
        const __nv_bfloat16* v = Vg + (size_t)kt * BK;
        const __nv_bfloat16* e = Eg + (size_t)kt * BK;
        #pragma unroll
        for (int i = 0; i < 8; i++) {
            const int r = lrow + i*32;
            cp16(vs + swz(r*ROWB + lcol), (const char*)(v + (size_t)r * NDIM) + lcol);
        }
        #pragma unroll
        for (int i = 0; i < 4; i++) {
            const int r = lrow + i*32;
            cp16(es + swz(r*ROWB + lcol), (const char*)(e + (size_t)r * NDIM) + lcol);
        }
        cp_commit();
    };

    float acc[4][8][4] = {};
    load_tile(0, 0);
    load_tile(1, 1);
    load_tile(2, 2);

    for (int kt = 0; kt < Kt; kt++) {
        // pending groups are a subset of {kt, kt+1, kt+2}
        if (kt <= Kt - 3)      cp_wait<2>();
        else if (kt == Kt - 2) cp_wait<1>();
        else                   cp_wait<0>();
        __syncthreads();
        // stage (kt+3)%4 == (kt-1)%4 was consumed last iteration; safe after sync
        if (kt + 3 < Kt) load_tile((kt + 3) % O_STAGES, kt + 3);

        const uint32_t vs = sbase + (kt % O_STAGES) * O_STAGE_B;
        const uint32_t es = vs + O_A_BYTES;

        #pragma unroll
        for (int kk = 0; kk < BK; kk += 16) {
            uint32_t af[4][4];
            #pragma unroll
            for (int mi = 0; mi < 4; mi++) {
                const int row = wm*64 + mi*16 + a_r;
                ldsm4(af[mi], vs + swz(row*ROWB + kk*2 + a_c));
            }
            uint32_t bfr[4][4];
            #pragma unroll
            for (int nj = 0; nj < 4; nj++) {
                const int row = wn*64 + nj*16 + b_r;
                ldsm4(bfr[nj], es + swz(row*ROWB + kk*2 + b_c));
            }
            #pragma unroll
            for (int mi = 0; mi < 4; mi++)
                #pragma unroll
                for (int nj = 0; nj < 4; nj++) {
                    mma16816(acc[mi][2*nj  ], af[mi], &bfr[nj][0]);
                    mma16816(acc[mi][2*nj+1], af[mi], &bfr[nj][2]);
                }
        }
    }

    const float gm = gma[0];
    const int r = lane >> 2, q = lane & 3;
    #pragma unroll
    for (int ni = 0; ni < 8; ni++) {
        const int n = n0 + wn*64 + ni*8 + 2*q;
        const float sc0 = gm * g_rsum[b][n];
        const float sc1 = gm * g_rsum[b][n + 1];
        #pragma unroll
        for (int mi = 0; mi < 4; mi++) {
            const int m = m0 + wm*64 + mi*16 + r;
            const size_t i0 = ((size_t)(b*CDIM + m)) * NDIM + n;
            const size_t i8 = i0 + (size_t)8 * NDIM;
            float2 x0 = *(const float2*)&xin[i0];
            float2 x8 = *(const float2*)&xin[i8];
            *(float2*)&out[i0] = make_float2(sc0 * acc[mi][ni][0] + x0.x, sc1 * acc[mi][ni][1] + x0.y);
            *(float2*)&out[i8] = make_float2(sc0 * acc[mi][ni][2] + x8.x, sc1 * acc[mi][ni][3] + x8.y);
        }
    }
}

// ---------------- launch: fork V-projection onto a side stream ----------------
extern "C" void kernel_launch(void* const* d_in, const int* in_sizes, int n_in,
                              void* d_out, int out_size) {
    const float* x  = (const float*)d_in[0];
    // d_in[1] = s (unused by the reference)
    const float* wq = (const float*)d_in[2];
    const float* bq = (const float*)d_in[3];
    const float* wk = (const float*)d_in[4];
    const float* bk = (const float*)d_in[5];
    const float* wv = (const float*)d_in[6];
    const float* bv = (const float*)d_in[7];
    const float* gm = (const float*)d_in[8];
    float* out = (float*)d_out;

    cudaFuncSetAttribute(k_gemm_qk, cudaFuncAttributeMaxDynamicSharedMemorySize, SMEM_BYTES);
    cudaFuncSetAttribute(k_gemm_v,  cudaFuncAttributeMaxDynamicSharedMemorySize, SMEM_BYTES);
    cudaFuncSetAttribute(k_gemm_s,  cudaFuncAttributeMaxDynamicSharedMemorySize, SMEM_BYTES);
    cudaFuncSetAttribute(k_gemm_o,  cudaFuncAttributeMaxDynamicSharedMemorySize, O_SMEM);

    // side stream + fork/join events (host-side objects; created per call, capture-safe)
    cudaStream_t sv;
    cudaStreamCreateWithFlags(&sv, cudaStreamNonBlocking);
    cudaEvent_t eBase, eV;
    cudaEventCreateWithFlags(&eBase, cudaEventDisableTiming);
    cudaEventCreateWithFlags(&eV,    cudaEventDisableTiming);

    k_convert_x<<<dim3(128, 16, 2), dim3(32, 8)>>>(x);
    k_convert_w<<<1281, 256>>>(wq, wk, wv, bq, bk);
    cudaEventRecord(eBase, 0);

    // fork: V projection runs concurrently with QK -> S -> rowsum
    cudaStreamWaitEvent(sv, eBase, 0);
    k_gemm_v<<<dim3(32, 4, 2), 256, SMEM_BYTES, sv>>>(bv);
    cudaEventRecord(eV, sv);

    k_gemm_qk<<<dim3(1, 32, 2),  256, SMEM_BYTES>>>();
    k_gemm_s <<<dim3(32, 32, 2), 256, SMEM_BYTES>>>();
    k_rowsum <<<32, 256>>>();

    // join: O needs V, E, rowsum
    cudaStreamWaitEvent(0, eV, 0);
    k_gemm_o <<<dim3(32, 2, 2),  256, O_SMEM>>>(x, gm, out);
}